// round 1
// baseline (speedup 1.0000x reference)
#include <cuda_runtime.h>

// DigitCaps broadcasted batched matvec:
//   u_hat[b,r,c,o] = sum_i W[r,c,o,i] * x[b,r,i] + bias[o]
// B=512, R=1152, C=10, O=16, I=8, fp32.
//
// Strategy: output-store-bound kernel (377.5 MB out). Batch-tile 8 b's per
// thread in registers so every W load is amortized over 32 outputs, keeping
// W traffic L1/L2-resident instead of 3 GB of L2 re-reads.

#define DC_B 512
#define DC_R 1152
#define DC_C 10
#define DC_O 16
#define DC_I 8

#define BTILE 8              // batch elements per thread
#define RTILE 32             // r values per block
// block = 4 (o-quads) * RTILE threads = 128

__global__ __launch_bounds__(128, 1)
void digitcaps_kernel(const float* __restrict__ x,
                      const float* __restrict__ W,
                      const float* __restrict__ bias,
                      float* __restrict__ out)
{
    const int o4      = threadIdx.x & 3;        // which group of 4 output dims
    const int r_local = threadIdx.x >> 2;       // 0..31
    const int r       = blockIdx.x * RTILE + r_local;
    const int b0      = blockIdx.y * BTILE;

    // bias for our 4 output dims (bias is [O,1] contiguous = [O])
    const float4 bb = *reinterpret_cast<const float4*>(bias + o4 * 4);

    // Load x[b0+k, r, 0:8] for 8 batch elements -> 64 registers.
    // Warp lanes share b across o4 (L1 broadcast) and cover 8 consecutive r
    // (256B contiguous runs) -> well coalesced.
    float4 xv0[BTILE], xv1[BTILE];
#pragma unroll
    for (int k = 0; k < BTILE; ++k) {
        const float4* xp = reinterpret_cast<const float4*>(
            x + ((size_t)(b0 + k) * DC_R + r) * DC_I);
        xv0[k] = xp[0];
        xv1[k] = xp[1];
    }

    // W[r, c, o, i] with c,o,i contiguous: row r starts at r*C*O*I.
    const float* Wr = W + (size_t)r * (DC_C * DC_O * DC_I) + (size_t)o4 * 4 * DC_I;

    // Output base for (b, r): ((b*R + r)*C + c)*O + o
    const size_t out_rbase = (size_t)r * DC_C * DC_O + (size_t)o4 * 4;

#pragma unroll
    for (int c = 0; c < DC_C; ++c) {
        // W tile for this (r, c, o4): 4 output rows x 8 inputs = 32 floats,
        // contiguous 128B. L1-resident across the batch dimension.
        const float4* wp = reinterpret_cast<const float4*>(Wr + c * (DC_O * DC_I));
        float4 w0a = wp[0], w0b = wp[1];   // o = o4*4 + 0
        float4 w1a = wp[2], w1b = wp[3];   // o = o4*4 + 1
        float4 w2a = wp[4], w2b = wp[5];   // o = o4*4 + 2
        float4 w3a = wp[6], w3b = wp[7];   // o = o4*4 + 3

#pragma unroll
        for (int k = 0; k < BTILE; ++k) {
            const float4 xa = xv0[k];
            const float4 xb = xv1[k];

            float4 acc;
            acc.x = fmaf(w0a.x, xa.x, fmaf(w0a.y, xa.y,
                    fmaf(w0a.z, xa.z, fmaf(w0a.w, xa.w,
                    fmaf(w0b.x, xb.x, fmaf(w0b.y, xb.y,
                    fmaf(w0b.z, xb.z, fmaf(w0b.w, xb.w, bb.x))))))));
            acc.y = fmaf(w1a.x, xa.x, fmaf(w1a.y, xa.y,
                    fmaf(w1a.z, xa.z, fmaf(w1a.w, xa.w,
                    fmaf(w1b.x, xb.x, fmaf(w1b.y, xb.y,
                    fmaf(w1b.z, xb.z, fmaf(w1b.w, xb.w, bb.y))))))));
            acc.z = fmaf(w2a.x, xa.x, fmaf(w2a.y, xa.y,
                    fmaf(w2a.z, xa.z, fmaf(w2a.w, xa.w,
                    fmaf(w2b.x, xb.x, fmaf(w2b.y, xb.y,
                    fmaf(w2b.z, xb.z, fmaf(w2b.w, xb.w, bb.z))))))));
            acc.w = fmaf(w3a.x, xa.x, fmaf(w3a.y, xa.y,
                    fmaf(w3a.z, xa.z, fmaf(w3a.w, xa.w,
                    fmaf(w3b.x, xb.x, fmaf(w3b.y, xb.y,
                    fmaf(w3b.z, xb.z, fmaf(w3b.w, xb.w, bb.w))))))));

            float4* op = reinterpret_cast<float4*>(
                out + (size_t)(b0 + k) * (DC_R * DC_C * DC_O)
                    + out_rbase + (size_t)c * DC_O);
            *op = acc;
        }
    }
}

extern "C" void kernel_launch(void* const* d_in, const int* in_sizes, int n_in,
                              void* d_out, int out_size)
{
    const float* x    = (const float*)d_in[0];  // [B, R, I]
    const float* W    = (const float*)d_in[1];  // [1, R, C, O, I]
    const float* bias = (const float*)d_in[2];  // [O, 1]
    float* out = (float*)d_out;                 // [B, R, C, O, 1]

    dim3 block(128, 1, 1);
    dim3 grid(DC_R / RTILE, DC_B / BTILE, 1);   // (36, 64)
    digitcaps_kernel<<<grid, block>>>(x, W, bias, out);
}

// round 3
// speedup vs baseline: 1.7413x; 1.7413x over previous
#include <cuda_runtime.h>

// DigitCaps broadcasted batched matvec:
//   u_hat[b,r,c,o] = sum_i W[r,c,o,i] * x[b,r,i] + bias[o]
// B=512, R=1152, C=10, O=16, I=8, fp32.
//
// R2: L1-wavefront-aware restructure. Round-1 kernel was L1-bound (80%) on
// per-thread W LDG.128 (32 distinct lines per warp instr). Now W is staged in
// shared memory with a bank-padded layout (36-float row stride -> 8 distinct
// (c,o4) rows per LDS.128 hit distinct bank groups, 4-way broadcast over
// b-groups), and stores are arranged so each STG.128 warp instr covers
// 4 x 128B contiguous segments (the coalescing floor).
//
// Mapping: block = 256 threads = 8 warps. Warp w handles r = r0 + w.
// Lane = bg(4) x c2(2) x o4(4):  lane = bg*8 + c2*4 + o4.
// Each thread covers 4 batch elems: b = b0 + k*4 + bg, k = 0..3 (x in regs).

#define DC_B 512
#define DC_R 1152
#define DC_C 10
#define DC_O 16
#define DC_I 8

#define RB 8     // r rows per block (one per warp)
#define BT 16    // batch elems per block
// smem W: 8r * 10c * 4(o4) rows of 36 floats (32 data + 4 pad) = 11520 floats
// smem x: 16 b * 68 floats (64 data + 4 pad)                   =  1088 floats
#define SW_FLOATS 11520
#define SX_FLOATS 1088
#define SMEM_BYTES ((SW_FLOATS + SX_FLOATS) * 4)

__global__ __launch_bounds__(256, 2)
void digitcaps_kernel(const float* __restrict__ x,
                      const float* __restrict__ W,
                      const float* __restrict__ bias,
                      float* __restrict__ out)
{
    extern __shared__ float smem[];
    float* sW = smem;                 // [g][36], g = (r_local*10 + c)*4 + o4
    float* sx = smem + SW_FLOATS;     // [b_local][68]: 8 r * 8 i + pad

    const int tid = threadIdx.x;
    const int r0  = blockIdx.x * RB;
    const int b0  = blockIdx.y * BT;

    // ---- cooperative W load: 8 r rows * 1280 floats = 2560 float4, coalesced ----
    {
        const float4* Wg = reinterpret_cast<const float4*>(W + (size_t)r0 * (DC_C * DC_O * DC_I));
#pragma unroll
        for (int q4 = 0; q4 < 10; ++q4) {
            const int q = q4 * 256 + tid;           // float4 index in W tile
            const float4 v = Wg[q];
            // q -> (rc, o, ih): flat = ((rc)*16 + o)*2 + ih
            const int ih = q & 1;
            const int o  = (q >> 1) & 15;
            const int rc = q >> 5;                   // r_local*10 + c
            const int g  = rc * 4 + (o >> 2);
            *reinterpret_cast<float4*>(sW + g * 36 + (o & 3) * 8 + ih * 4) = v;
        }
    }
    // ---- cooperative x load: 16 b * 64 floats = 256 float4, coalesced ----
    {
        const int b_i = tid >> 4;
        const int m   = tid & 15;                    // float4 index within b's 64-float chunk
        const float4 v = *reinterpret_cast<const float4*>(
            x + ((size_t)(b0 + b_i) * DC_R + r0) * DC_I + m * 4);
        *reinterpret_cast<float4*>(sx + b_i * 68 + m * 4) = v;
    }
    __syncthreads();

    const int lane = tid & 31;
    const int w    = tid >> 5;       // warp id == r_local
    const int bg   = lane >> 3;      // 0..3 batch group
    const int c2   = (lane >> 2) & 1;
    const int o4   = lane & 3;

    const int r = r0 + w;

    // x for this thread's 4 batch elements (broadcast LDS, 4 distinct addrs)
    float4 xa[4], xb[4];
#pragma unroll
    for (int k = 0; k < 4; ++k) {
        const int bl = k * 4 + bg;
        xa[k] = *reinterpret_cast<const float4*>(sx + bl * 68 + w * 8);
        xb[k] = *reinterpret_cast<const float4*>(sx + bl * 68 + w * 8 + 4);
    }

    const float4 bb = *reinterpret_cast<const float4*>(bias + o4 * 4);

    // out element offset: ((b*R + r)*C + c)*O + o
    const size_t out_r = (size_t)r * (DC_C * DC_O);

#pragma unroll
    for (int cp = 0; cp < 5; ++cp) {
        const int c = cp * 2 + c2;
        // W row for (r, c, o4): 32 floats = 4 o * 8 i. 8 distinct rows per warp,
        // row stride 36 floats (== 4 mod 32) -> conflict-free bank groups.
        const float* wr = sW + ((w * DC_C + c) * 4 + o4) * 36;
        const float4 w0a = *reinterpret_cast<const float4*>(wr + 0);
        const float4 w0b = *reinterpret_cast<const float4*>(wr + 4);
        const float4 w1a = *reinterpret_cast<const float4*>(wr + 8);
        const float4 w1b = *reinterpret_cast<const float4*>(wr + 12);
        const float4 w2a = *reinterpret_cast<const float4*>(wr + 16);
        const float4 w2b = *reinterpret_cast<const float4*>(wr + 20);
        const float4 w3a = *reinterpret_cast<const float4*>(wr + 24);
        const float4 w3b = *reinterpret_cast<const float4*>(wr + 28);

#pragma unroll
        for (int k = 0; k < 4; ++k) {
            const float4 va = xa[k];
            const float4 vb = xb[k];
            float4 acc;
            acc.x = fmaf(w0a.x, va.x, fmaf(w0a.y, va.y,
                    fmaf(w0a.z, va.z, fmaf(w0a.w, va.w,
                    fmaf(w0b.x, vb.x, fmaf(w0b.y, vb.y,
                    fmaf(w0b.z, vb.z, fmaf(w0b.w, vb.w, bb.x))))))));
            acc.y = fmaf(w1a.x, va.x, fmaf(w1a.y, va.y,
                    fmaf(w1a.z, va.z, fmaf(w1a.w, va.w,
                    fmaf(w1b.x, vb.x, fmaf(w1b.y, vb.y,
                    fmaf(w1b.z, vb.z, fmaf(w1b.w, vb.w, bb.y))))))));
            acc.z = fmaf(w2a.x, va.x, fmaf(w2a.y, va.y,
                    fmaf(w2a.z, va.z, fmaf(w2a.w, va.w,
                    fmaf(w2b.x, vb.x, fmaf(w2b.y, vb.y,
                    fmaf(w2b.z, vb.z, fmaf(w2b.w, vb.w, bb.z))))))));
            acc.w = fmaf(w3a.x, va.x, fmaf(w3a.y, va.y,
                    fmaf(w3a.z, va.z, fmaf(w3a.w, va.w,
                    fmaf(w3b.x, vb.x, fmaf(w3b.y, vb.y,
                    fmaf(w3b.z, vb.z, fmaf(w3b.w, vb.w, bb.w))))))));

            const int b = b0 + k * 4 + bg;
            // Per STG warp instr (fixed k): bg segments of 128B (c2*64B + o4*16B
            // contiguous within segment) -> 4 wavefronts.
            float4* op = reinterpret_cast<float4*>(
                out + (size_t)b * (DC_R * DC_C * DC_O) + out_r
                    + (size_t)c * DC_O + o4 * 4);
            *op = acc;
        }
    }
}

extern "C" void kernel_launch(void* const* d_in, const int* in_sizes, int n_in,
                              void* d_out, int out_size)
{
    const float* x    = (const float*)d_in[0];  // [B, R, I]
    const float* W    = (const float*)d_in[1];  // [1, R, C, O, I]
    const float* bias = (const float*)d_in[2];  // [O, 1]
    float* out = (float*)d_out;                 // [B, R, C, O, 1]

    cudaFuncSetAttribute(digitcaps_kernel,
                         cudaFuncAttributeMaxDynamicSharedMemorySize, SMEM_BYTES);

    dim3 block(256, 1, 1);
    dim3 grid(DC_R / RB, DC_B / BT, 1);   // (144, 32)
    digitcaps_kernel<<<grid, block, SMEM_BYTES>>>(x, W, bias, out);
}